// round 11
// baseline (speedup 1.0000x reference)
#include <cuda_runtime.h>
#include <cuda_bf16.h>

#define NN   50000
#define NE   1600000
#define NR   8
#define KC   1152        // NR*128 + 128
#define CAP  16384
#define NP   256
#define DOUT 64

// ---- scratch (zero-initialized once by CUDA) ----
__device__ int   g_pmap[NN];          // 1 = pooled dst (idempotent across runs)
__device__ int   g_nf[NN];            // 1 = needed node (idempotent across runs)
__device__ int   g_cid[NN];
__device__ int   g_nodes[CAP];
__device__ int   g_counter;           // reset each run in k_mark_pool
__device__ unsigned g_done;           // pool-block ticket; last block resets to 0
__device__ int   g_head[NR * NN];     // head = edge+1, 0 = empty; CLEARED each run
__device__ int2  g_en[NE];            // {src, next(edge+1 or 0)}, rewritten each run
__device__ __align__(16) __nv_bfloat16 g_Ahi[(size_t)CAP * KC];
__device__ __align__(16) __nv_bfloat16 g_Alo[(size_t)CAP * KC];
__device__ __align__(16) __nv_bfloat16 g_Bhi[128 * KC];   // [outcol h][k]
__device__ __align__(16) __nv_bfloat16 g_Blo[128 * KC];
__device__ float g_h[(size_t)CAP * 128];
__device__ float g_part[NP * DOUT];
__device__ float g_wp[NP];

static __device__ __forceinline__ void split2(float v, __nv_bfloat16& hi, __nv_bfloat16& lo) {
    hi = __float2bfloat16_rn(v);
    lo = __float2bfloat16_rn(v - __bfloat162float(hi));
}

// warp mma m16n8k16 bf16 -> f32 accum (baseline PTX, HMMA on sm_103)
#define MMA16816(c, a, b) \
    asm volatile("mma.sync.aligned.m16n8k16.row.col.f32.bf16.bf16.f32 " \
                 "{%0,%1,%2,%3},{%4,%5,%6,%7},{%8,%9},{%0,%1,%2,%3};" \
                 : "+f"((c)[0]), "+f"((c)[1]), "+f"((c)[2]), "+f"((c)[3]) \
                 : "r"((a)[0]), "r"((a)[1]), "r"((a)[2]), "r"((a)[3]), \
                   "r"((b)[0]), "r"((b)[1]))

// ------------------------------------------- kernel 1: mark pool + resets
__global__ void k_mark_pool(const int* __restrict__ pool) {
    int p = pool[threadIdx.x];
    g_pmap[p] = 1;
    g_nf[p]   = 1;
    if (threadIdx.x == 0) { g_counter = 0; g_done = 0; }
}

// --------------------- kernel 2: mark_src || wsplit || head-clear
#define NB_MS ((NE + 255) / 256)
#define NB_WS ((128 * KC + 255) / 256)
#define NB_HC ((NR * NN / 4 + 255) / 256)    // clear as int4
__global__ void k_mark_ws(const int* __restrict__ ei,
                          const float* __restrict__ W1,
                          const float* __restrict__ root1) {
    int b = blockIdx.x;
    if (b < NB_MS) {
        int e = b * 256 + threadIdx.x;
        if (e < NE) {
            int dst = ei[NE + e];
            if (g_pmap[dst]) g_nf[ei[e]] = 1;
        }
    } else if (b < NB_MS + NB_WS) {
        int idx = (b - NB_MS) * 256 + threadIdx.x;   // 128*KC
        if (idx < 128 * KC) {
            int h = idx / KC, k = idx - h * KC;
            float w = (k < 1024) ? W1[k * 128 + h] : root1[(k - 1024) * 128 + h];
            __nv_bfloat16 hi, lo;
            split2(w, hi, lo);
            g_Bhi[idx] = hi;
            g_Blo[idx] = lo;
        }
    } else {
        int idx = (b - NB_MS - NB_WS) * 256 + threadIdx.x;   // int4 index
        if (idx < NR * NN / 4)
            ((int4*)g_head)[idx] = make_int4(0, 0, 0, 0);
    }
}

// ------------------------------------------- kernel 3: compact || build
#define NB_CP ((NN + 255) / 256)
__global__ void k_cb(const int* __restrict__ ei, const int* __restrict__ et) {
    int b = blockIdx.x;
    if (b < NB_CP) {
        int v = b * 256 + threadIdx.x;
        int lane = threadIdx.x & 31;
        int pred = (v < NN) && g_nf[v];
        unsigned mask = __ballot_sync(0xFFFFFFFF, pred);
        if (mask) {
            int leader = __ffs(mask) - 1;
            int base = 0;
            if (lane == leader) base = atomicAdd(&g_counter, __popc(mask));
            base = __shfl_sync(0xFFFFFFFF, base, leader);
            if (pred) {
                int c = base + __popc(mask & ((1u << lane) - 1));
                if (c < CAP) { g_cid[v] = c; g_nodes[c] = v; }
            }
        }
    } else {
        int e = (b - NB_CP) * 256 + threadIdx.x;
        if (e < NE) {
            int dst = ei[NE + e];
            if (g_nf[dst]) {
                int r = et[e];
                int prev = atomicExch(&g_head[r * NN + dst], e + 1);
                g_en[e] = make_int2(ei[e], prev);   // {src, next}
            }
        }
    }
}

// ------------------------------------------- kernel 4: layer-1 aggregation
// Task-per-warp, THREE tasks walked concurrently per warp; each chain hop is
// a single int2 load {src, next} (packed in k_cb).
__global__ void __launch_bounds__(256) k_agg1(const float* __restrict__ x) {
    const float4* x4 = (const float4*)x;
    int wid   = (blockIdx.x * blockDim.x + threadIdx.x) >> 5;
    int lane  = threadIdx.x & 31;
    int nwarp = (gridDim.x * blockDim.x) >> 5;
    int cnt   = min(g_counter, CAP);
    int ntask = cnt * 9;

    for (int base = wid * 3; base < ntask; base += nwarp * 3) {
        int    ptr_ [3];
        int    c_   [3];
        float4 acc_ [3];
        bool   chain[3];
#pragma unroll
        for (int s = 0; s < 3; s++) {
            int tt = base + s;
            ptr_[s] = 0;
            c_[s]   = 0;
            acc_[s] = make_float4(0.f, 0.f, 0.f, 0.f);
            chain[s] = false;
            if (tt < ntask) {
                int i = tt / 9;
                int r = tt - i * 9;
                int v = g_nodes[i];
                if (r == 8) {
                    acc_[s] = x4[v * 32 + lane];   // self row
                } else {
                    ptr_[s] = g_head[r * NN + v];
                    chain[s] = true;
                }
            }
        }

        // walk three chains concurrently; one 8B load per hop
        while (ptr_[0] | ptr_[1] | ptr_[2]) {
            int2 sn[3];
#pragma unroll
            for (int s = 0; s < 3; s++)
                if (ptr_[s]) sn[s] = g_en[ptr_[s] - 1];
#pragma unroll
            for (int s = 0; s < 3; s++) {
                if (ptr_[s]) {
                    float4 xv = x4[sn[s].x * 32 + lane];
                    acc_[s].x += xv.x; acc_[s].y += xv.y;
                    acc_[s].z += xv.z; acc_[s].w += xv.w;
                    c_[s]++;
                    ptr_[s] = sn[s].y;
                }
            }
        }

#pragma unroll
        for (int s = 0; s < 3; s++) {
            int tt = base + s;
            if (tt >= ntask) continue;
            int i = tt / 9;
            int r = tt - i * 9;
            float4 a = acc_[s];
            if (chain[s] && c_[s] > 1) {
                float sc = 1.0f / (float)c_[s];
                a.x *= sc; a.y *= sc; a.z *= sc; a.w *= sc;
            }
            __nv_bfloat16 h[4], l[4];
            split2(a.x, h[0], l[0]);
            split2(a.y, h[1], l[1]);
            split2(a.z, h[2], l[2]);
            split2(a.w, h[3], l[3]);
            size_t off = (size_t)i * KC + r * 128 + lane * 4;
            *(uint2*)&g_Ahi[off] = *(uint2*)h;
            *(uint2*)&g_Alo[off] = *(uint2*)l;
        }
    }
}

// ------------------------------------------- kernel 5: layer-1 GEMM (HMMA)
#define SA 40
__global__ void __launch_bounds__(256) k_gemm1h(const float* __restrict__ b1) {
    __shared__ __align__(16) __nv_bfloat16 As[2][64 * SA];
    __shared__ __align__(16) __nv_bfloat16 Bs[2][128 * SA];
    int cnt  = min(g_counter, CAP);
    int row0 = blockIdx.x * 64;
    if (row0 >= cnt) return;
    int t = threadIdx.x;
    int lane = t & 31, wid = t >> 5;
    int wm = (wid & 1) * 32;
    int wn = (wid >> 1) * 32;
    int gr4 = lane >> 2;
    int kc  = (lane & 3) * 2;

    float acc[2][4][4];
#pragma unroll
    for (int mt = 0; mt < 2; mt++)
#pragma unroll
        for (int nt = 0; nt < 4; nt++)
#pragma unroll
            for (int j = 0; j < 4; j++) acc[mt][nt][j] = 0.f;

    for (int c = 0; c < KC / 32; c++) {
        {
            int row = t >> 2, q = t & 3;
            int gr = row0 + row;
            uint4 vh = make_uint4(0u, 0u, 0u, 0u), vl = vh;
            if (gr < cnt) {
                size_t s = (size_t)gr * KC + c * 32 + q * 8;
                vh = *(const uint4*)&g_Ahi[s];
                vl = *(const uint4*)&g_Alo[s];
            }
            *(uint4*)&As[0][row * SA + q * 8] = vh;
            *(uint4*)&As[1][row * SA + q * 8] = vl;
        }
#pragma unroll
        for (int q2 = 0; q2 < 2; q2++) {
            int idx = t + q2 * 256;
            int h = idx >> 2, q = idx & 3;
            size_t s = (size_t)h * KC + c * 32 + q * 8;
            *(uint4*)&Bs[0][h * SA + q * 8] = *(const uint4*)&g_Bhi[s];
            *(uint4*)&Bs[1][h * SA + q * 8] = *(const uint4*)&g_Blo[s];
        }
        __syncthreads();

#pragma unroll
        for (int ks = 0; ks < 32; ks += 16) {
            unsigned ah[2][4], al[2][4], bh[4][2], bl[4][2];
#pragma unroll
            for (int mt = 0; mt < 2; mt++) {
                int r0 = wm + mt * 16 + gr4;
                ah[mt][0] = *(const unsigned*)&As[0][(r0    ) * SA + ks + kc];
                ah[mt][1] = *(const unsigned*)&As[0][(r0 + 8) * SA + ks + kc];
                ah[mt][2] = *(const unsigned*)&As[0][(r0    ) * SA + ks + kc + 8];
                ah[mt][3] = *(const unsigned*)&As[0][(r0 + 8) * SA + ks + kc + 8];
                al[mt][0] = *(const unsigned*)&As[1][(r0    ) * SA + ks + kc];
                al[mt][1] = *(const unsigned*)&As[1][(r0 + 8) * SA + ks + kc];
                al[mt][2] = *(const unsigned*)&As[1][(r0    ) * SA + ks + kc + 8];
                al[mt][3] = *(const unsigned*)&As[1][(r0 + 8) * SA + ks + kc + 8];
            }
#pragma unroll
            for (int nt = 0; nt < 4; nt++) {
                int n0 = wn + nt * 8 + gr4;
                bh[nt][0] = *(const unsigned*)&Bs[0][n0 * SA + ks + kc];
                bh[nt][1] = *(const unsigned*)&Bs[0][n0 * SA + ks + kc + 8];
                bl[nt][0] = *(const unsigned*)&Bs[1][n0 * SA + ks + kc];
                bl[nt][1] = *(const unsigned*)&Bs[1][n0 * SA + ks + kc + 8];
            }
#pragma unroll
            for (int mt = 0; mt < 2; mt++)
#pragma unroll
                for (int nt = 0; nt < 4; nt++) {
                    MMA16816(acc[mt][nt], ah[mt], bh[nt]);
                    MMA16816(acc[mt][nt], al[mt], bh[nt]);
                    MMA16816(acc[mt][nt], ah[mt], bl[nt]);
                }
        }
        __syncthreads();
    }

#pragma unroll
    for (int mt = 0; mt < 2; mt++) {
#pragma unroll
        for (int nt = 0; nt < 4; nt++) {
            int col = wn + nt * 8 + kc;
            float b0 = b1[col], b1v = b1[col + 1];
            int r0 = row0 + wm + mt * 16 + gr4;
            int r1 = r0 + 8;
            if (r0 < cnt) {
                float2 o;
                o.x = fmaxf(acc[mt][nt][0] + b0, 0.f);
                o.y = fmaxf(acc[mt][nt][1] + b1v, 0.f);
                *(float2*)&g_h[(size_t)r0 * 128 + col] = o;
            }
            if (r1 < cnt) {
                float2 o;
                o.x = fmaxf(acc[mt][nt][2] + b0, 0.f);
                o.y = fmaxf(acc[mt][nt][3] + b1v, 0.f);
                *(float2*)&g_h[(size_t)r1 * 128 + col] = o;
            }
        }
    }
}

// ------------------------------------------- kernel 6: layer-2 + pool + final
__global__ void __launch_bounds__(256) k_pool(const float* __restrict__ x,
                                              const int* __restrict__ pool,
                                              const float* __restrict__ W2,
                                              const float* __restrict__ root2,
                                              const float* __restrict__ b2,
                                              float* __restrict__ out) {
    __shared__ float cs[KC];
    __shared__ float red[256];
    __shared__ unsigned s_ticket;
    const float4* h4 = (const float4*)g_h;
    int p = pool[blockIdx.x];
    int t = threadIdx.x;
    int lane = t & 31, w = t >> 5;

    {
        int r = w;
        int ptr = g_head[r * NN + p];
        int c = 0;
        float4 acc = make_float4(0.f, 0.f, 0.f, 0.f);
        while (ptr) {
            int2 sn = g_en[ptr - 1];
            int ci = g_cid[sn.x];
            float4 hv = h4[ci * 32 + lane];
            acc.x += hv.x; acc.y += hv.y; acc.z += hv.z; acc.w += hv.w;
            c++;
            ptr = sn.y;
        }
        if (c > 1) {
            float s = 1.0f / (float)c;
            acc.x *= s; acc.y *= s; acc.z *= s; acc.w *= s;
        }
        *(float4*)&cs[r * 128 + lane * 4] = acc;
    }
    if (t < 128) {
        int cp = g_cid[p];
        cs[1024 + t] = g_h[(size_t)cp * 128 + t];
    }
    __syncthreads();

    int j = t & 63, q = t >> 6;
    float s = 0.f;
    int k0 = q * 288;
#pragma unroll 4
    for (int k = k0; k < k0 + 288; k++) {
        float wv = (k < 1024) ? W2[k * 64 + j] : root2[(k - 1024) * 64 + j];
        s += cs[k] * wv;
    }
    red[t] = s;
    __syncthreads();
    if (t < 64) {
        float o = red[t] + red[t + 64] + red[t + 128] + red[t + 192] + b2[j];
        float wp = 4.f * x[p * 128 + 0] + x[p * 128 + 1] + 2.f * x[p * 128 + 2];
        g_part[blockIdx.x * 64 + j] = o * wp;
        if (j == 0) g_wp[blockIdx.x] = wp;
    }

    // ---- last-block final reduction ----
    __threadfence();
    __syncthreads();
    if (t == 0) s_ticket = atomicAdd(&g_done, 1);
    __syncthreads();
    if (s_ticket == NP - 1) {
        __threadfence();
        if (t < 64) {
            float acc = 0.f;
            for (int i = 0; i < NP; i++) acc += g_part[i * 64 + t];
            float ws = 0.f;
            for (int i = 0; i < NP; i++) ws += g_wp[i];
            out[t] = acc / (ws + 1e-9f);
        }
        if (t == 0) g_done = 0;   // reset for next replay
    }
}

// ---------------------------------------------------------------- launch
extern "C" void kernel_launch(void* const* d_in, const int* in_sizes, int n_in,
                              void* d_out, int out_size) {
    const float* x     = (const float*)d_in[0];
    const int*   ei    = (const int*)  d_in[1];
    const int*   et    = (const int*)  d_in[2];
    const int*   pool  = (const int*)  d_in[3];
    const float* W1    = (const float*)d_in[4];
    const float* root1 = (const float*)d_in[5];
    const float* b1    = (const float*)d_in[6];
    const float* W2    = (const float*)d_in[7];
    const float* root2 = (const float*)d_in[8];
    const float* b2    = (const float*)d_in[9];
    float* out = (float*)d_out;
    (void)in_sizes; (void)n_in; (void)out_size;

    k_mark_pool<<<1, NP>>>(pool);
    k_mark_ws  <<<NB_MS + NB_WS + NB_HC, 256>>>(ei, W1, root1);
    k_cb       <<<NB_CP + NB_MS, 256>>>(ei, et);
    k_agg1     <<<2048, 256>>>(x);
    k_gemm1h   <<<CAP / 64, 256>>>(b1);
    k_pool     <<<NP, 256>>>(x, pool, W2, root2, b2, out);
}

// round 12
// speedup vs baseline: 1.0419x; 1.0419x over previous
#include <cuda_runtime.h>
#include <cuda_bf16.h>

#define NN   50000
#define NE   1600000
#define NR   8
#define KC   1152        // NR*128 + 128
#define CAP  16384
#define NP   256
#define DOUT 64

// ---- scratch (zero-initialized once by CUDA) ----
__device__ int   g_pmap[NN];          // 1 = pooled dst (idempotent across runs)
__device__ int   g_nf[NN];            // 1 = needed node (idempotent across runs)
__device__ int   g_cid[NN];
__device__ int   g_nodes[CAP];
__device__ int   g_counter;           // reset each run in k_mark_pool
__device__ unsigned g_done;           // pool-block ticket; last block resets to 0
__device__ int   g_head[NR * NN];     // head = edge+1, 0 = empty; CLEARED each run
__device__ int2  g_en[NE];            // {src, next(edge+1 or 0)}, rewritten each run
__device__ __align__(16) __nv_bfloat16 g_Ahi[(size_t)CAP * KC];
__device__ __align__(16) __nv_bfloat16 g_Alo[(size_t)CAP * KC];
__device__ __align__(16) __nv_bfloat16 g_Bhi[128 * KC];   // [outcol h][k]
__device__ __align__(16) __nv_bfloat16 g_Blo[128 * KC];
__device__ float g_h[(size_t)CAP * 128];
__device__ float g_part[NP * DOUT];
__device__ float g_wp[NP];

static __device__ __forceinline__ void split2(float v, __nv_bfloat16& hi, __nv_bfloat16& lo) {
    hi = __float2bfloat16_rn(v);
    lo = __float2bfloat16_rn(v - __bfloat162float(hi));
}

// warp mma m16n8k16 bf16 -> f32 accum (baseline PTX, HMMA on sm_103)
#define MMA16816(c, a, b) \
    asm volatile("mma.sync.aligned.m16n8k16.row.col.f32.bf16.bf16.f32 " \
                 "{%0,%1,%2,%3},{%4,%5,%6,%7},{%8,%9},{%0,%1,%2,%3};" \
                 : "+f"((c)[0]), "+f"((c)[1]), "+f"((c)[2]), "+f"((c)[3]) \
                 : "r"((a)[0]), "r"((a)[1]), "r"((a)[2]), "r"((a)[3]), \
                   "r"((b)[0]), "r"((b)[1]))

// ------------------------------------------- kernel 1: mark pool + resets
__global__ void k_mark_pool(const int* __restrict__ pool) {
    int p = pool[threadIdx.x];
    g_pmap[p] = 1;
    g_nf[p]   = 1;
    if (threadIdx.x == 0) { g_counter = 0; g_done = 0; }
}

// --------------------- kernel 2: mark_src || wsplit || head-clear
#define NB_MS ((NE + 255) / 256)
#define NB_WS ((128 * KC + 255) / 256)
#define NB_HC ((NR * NN / 4 + 255) / 256)    // clear as int4
__global__ void k_mark_ws(const int* __restrict__ ei,
                          const float* __restrict__ W1,
                          const float* __restrict__ root1) {
    int b = blockIdx.x;
    if (b < NB_MS) {
        int e = b * 256 + threadIdx.x;
        if (e < NE) {
            int dst = ei[NE + e];
            if (g_pmap[dst]) g_nf[ei[e]] = 1;
        }
    } else if (b < NB_MS + NB_WS) {
        int idx = (b - NB_MS) * 256 + threadIdx.x;   // 128*KC
        if (idx < 128 * KC) {
            int h = idx / KC, k = idx - h * KC;
            float w = (k < 1024) ? W1[k * 128 + h] : root1[(k - 1024) * 128 + h];
            __nv_bfloat16 hi, lo;
            split2(w, hi, lo);
            g_Bhi[idx] = hi;
            g_Blo[idx] = lo;
        }
    } else {
        int idx = (b - NB_MS - NB_WS) * 256 + threadIdx.x;   // int4 index
        if (idx < NR * NN / 4)
            ((int4*)g_head)[idx] = make_int4(0, 0, 0, 0);
    }
}

// ------------------------------------------- kernel 3: compact || build
#define NB_CP ((NN + 255) / 256)
__global__ void k_cb(const int* __restrict__ ei, const int* __restrict__ et) {
    int b = blockIdx.x;
    if (b < NB_CP) {
        int v = b * 256 + threadIdx.x;
        int lane = threadIdx.x & 31;
        int pred = (v < NN) && g_nf[v];
        unsigned mask = __ballot_sync(0xFFFFFFFF, pred);
        if (mask) {
            int leader = __ffs(mask) - 1;
            int base = 0;
            if (lane == leader) base = atomicAdd(&g_counter, __popc(mask));
            base = __shfl_sync(0xFFFFFFFF, base, leader);
            if (pred) {
                int c = base + __popc(mask & ((1u << lane) - 1));
                if (c < CAP) { g_cid[v] = c; g_nodes[c] = v; }
            }
        }
    } else {
        int e = (b - NB_CP) * 256 + threadIdx.x;
        if (e < NE) {
            int dst = ei[NE + e];
            if (g_nf[dst]) {
                int r = et[e];
                int prev = atomicExch(&g_head[r * NN + dst], e + 1);
                g_en[e] = make_int2(ei[e], prev);   // {src, next}
            }
        }
    }
}

// ------------------------------------------- kernel 4: layer-1 aggregation
// Task-per-warp, TWO tasks walked concurrently per warp (R10 shape);
// each chain hop is a single int2 load {src, next} (packed in k_cb).
__global__ void __launch_bounds__(256) k_agg1(const float* __restrict__ x) {
    const float4* x4 = (const float4*)x;
    int wid   = (blockIdx.x * blockDim.x + threadIdx.x) >> 5;
    int lane  = threadIdx.x & 31;
    int nwarp = (gridDim.x * blockDim.x) >> 5;
    int cnt   = min(g_counter, CAP);
    int ntask = cnt * 9;

    for (int base = wid * 2; base < ntask; base += nwarp * 2) {
        int    ptr_ [2];
        int    c_   [2];
        float4 acc_ [2];
        bool   chain[2];
#pragma unroll
        for (int s = 0; s < 2; s++) {
            int tt = base + s;
            ptr_[s] = 0;
            c_[s]   = 0;
            acc_[s] = make_float4(0.f, 0.f, 0.f, 0.f);
            chain[s] = false;
            if (tt < ntask) {
                int i = tt / 9;
                int r = tt - i * 9;
                int v = g_nodes[i];
                if (r == 8) {
                    acc_[s] = x4[v * 32 + lane];   // self row
                } else {
                    ptr_[s] = g_head[r * NN + v];
                    chain[s] = true;
                }
            }
        }

        // walk both chains concurrently; one 8B load per hop
        while (ptr_[0] | ptr_[1]) {
            int2 sn[2];
#pragma unroll
            for (int s = 0; s < 2; s++)
                if (ptr_[s]) sn[s] = g_en[ptr_[s] - 1];
#pragma unroll
            for (int s = 0; s < 2; s++) {
                if (ptr_[s]) {
                    float4 xv = x4[sn[s].x * 32 + lane];
                    acc_[s].x += xv.x; acc_[s].y += xv.y;
                    acc_[s].z += xv.z; acc_[s].w += xv.w;
                    c_[s]++;
                    ptr_[s] = sn[s].y;
                }
            }
        }

#pragma unroll
        for (int s = 0; s < 2; s++) {
            int tt = base + s;
            if (tt >= ntask) continue;
            int i = tt / 9;
            int r = tt - i * 9;
            float4 a = acc_[s];
            if (chain[s] && c_[s] > 1) {
                float sc = 1.0f / (float)c_[s];
                a.x *= sc; a.y *= sc; a.z *= sc; a.w *= sc;
            }
            __nv_bfloat16 h[4], l[4];
            split2(a.x, h[0], l[0]);
            split2(a.y, h[1], l[1]);
            split2(a.z, h[2], l[2]);
            split2(a.w, h[3], l[3]);
            size_t off = (size_t)i * KC + r * 128 + lane * 4;
            *(uint2*)&g_Ahi[off] = *(uint2*)h;
            *(uint2*)&g_Alo[off] = *(uint2*)l;
        }
    }
}

// ------------------------------------------- kernel 5: layer-1 GEMM (HMMA)
#define SA 40
__global__ void __launch_bounds__(256) k_gemm1h(const float* __restrict__ b1) {
    __shared__ __align__(16) __nv_bfloat16 As[2][64 * SA];
    __shared__ __align__(16) __nv_bfloat16 Bs[2][128 * SA];
    int cnt  = min(g_counter, CAP);
    int row0 = blockIdx.x * 64;
    if (row0 >= cnt) return;
    int t = threadIdx.x;
    int lane = t & 31, wid = t >> 5;
    int wm = (wid & 1) * 32;
    int wn = (wid >> 1) * 32;
    int gr4 = lane >> 2;
    int kc  = (lane & 3) * 2;

    float acc[2][4][4];
#pragma unroll
    for (int mt = 0; mt < 2; mt++)
#pragma unroll
        for (int nt = 0; nt < 4; nt++)
#pragma unroll
            for (int j = 0; j < 4; j++) acc[mt][nt][j] = 0.f;

    for (int c = 0; c < KC / 32; c++) {
        {
            int row = t >> 2, q = t & 3;
            int gr = row0 + row;
            uint4 vh = make_uint4(0u, 0u, 0u, 0u), vl = vh;
            if (gr < cnt) {
                size_t s = (size_t)gr * KC + c * 32 + q * 8;
                vh = *(const uint4*)&g_Ahi[s];
                vl = *(const uint4*)&g_Alo[s];
            }
            *(uint4*)&As[0][row * SA + q * 8] = vh;
            *(uint4*)&As[1][row * SA + q * 8] = vl;
        }
#pragma unroll
        for (int q2 = 0; q2 < 2; q2++) {
            int idx = t + q2 * 256;
            int h = idx >> 2, q = idx & 3;
            size_t s = (size_t)h * KC + c * 32 + q * 8;
            *(uint4*)&Bs[0][h * SA + q * 8] = *(const uint4*)&g_Bhi[s];
            *(uint4*)&Bs[1][h * SA + q * 8] = *(const uint4*)&g_Blo[s];
        }
        __syncthreads();

#pragma unroll
        for (int ks = 0; ks < 32; ks += 16) {
            unsigned ah[2][4], al[2][4], bh[4][2], bl[4][2];
#pragma unroll
            for (int mt = 0; mt < 2; mt++) {
                int r0 = wm + mt * 16 + gr4;
                ah[mt][0] = *(const unsigned*)&As[0][(r0    ) * SA + ks + kc];
                ah[mt][1] = *(const unsigned*)&As[0][(r0 + 8) * SA + ks + kc];
                ah[mt][2] = *(const unsigned*)&As[0][(r0    ) * SA + ks + kc + 8];
                ah[mt][3] = *(const unsigned*)&As[0][(r0 + 8) * SA + ks + kc + 8];
                al[mt][0] = *(const unsigned*)&As[1][(r0    ) * SA + ks + kc];
                al[mt][1] = *(const unsigned*)&As[1][(r0 + 8) * SA + ks + kc];
                al[mt][2] = *(const unsigned*)&As[1][(r0    ) * SA + ks + kc + 8];
                al[mt][3] = *(const unsigned*)&As[1][(r0 + 8) * SA + ks + kc + 8];
            }
#pragma unroll
            for (int nt = 0; nt < 4; nt++) {
                int n0 = wn + nt * 8 + gr4;
                bh[nt][0] = *(const unsigned*)&Bs[0][n0 * SA + ks + kc];
                bh[nt][1] = *(const unsigned*)&Bs[0][n0 * SA + ks + kc + 8];
                bl[nt][0] = *(const unsigned*)&Bs[1][n0 * SA + ks + kc];
                bl[nt][1] = *(const unsigned*)&Bs[1][n0 * SA + ks + kc + 8];
            }
#pragma unroll
            for (int mt = 0; mt < 2; mt++)
#pragma unroll
                for (int nt = 0; nt < 4; nt++) {
                    MMA16816(acc[mt][nt], ah[mt], bh[nt]);
                    MMA16816(acc[mt][nt], al[mt], bh[nt]);
                    MMA16816(acc[mt][nt], ah[mt], bl[nt]);
                }
        }
        __syncthreads();
    }

#pragma unroll
    for (int mt = 0; mt < 2; mt++) {
#pragma unroll
        for (int nt = 0; nt < 4; nt++) {
            int col = wn + nt * 8 + kc;
            float b0 = b1[col], b1v = b1[col + 1];
            int r0 = row0 + wm + mt * 16 + gr4;
            int r1 = r0 + 8;
            if (r0 < cnt) {
                float2 o;
                o.x = fmaxf(acc[mt][nt][0] + b0, 0.f);
                o.y = fmaxf(acc[mt][nt][1] + b1v, 0.f);
                *(float2*)&g_h[(size_t)r0 * 128 + col] = o;
            }
            if (r1 < cnt) {
                float2 o;
                o.x = fmaxf(acc[mt][nt][2] + b0, 0.f);
                o.y = fmaxf(acc[mt][nt][3] + b1v, 0.f);
                *(float2*)&g_h[(size_t)r1 * 128 + col] = o;
            }
        }
    }
}

// ------------------------------------------- kernel 6: layer-2 + pool + final
__global__ void __launch_bounds__(256) k_pool(const float* __restrict__ x,
                                              const int* __restrict__ pool,
                                              const float* __restrict__ W2,
                                              const float* __restrict__ root2,
                                              const float* __restrict__ b2,
                                              float* __restrict__ out) {
    __shared__ float cs[KC];
    __shared__ float red[256];
    __shared__ unsigned s_ticket;
    const float4* h4 = (const float4*)g_h;
    int p = pool[blockIdx.x];
    int t = threadIdx.x;
    int lane = t & 31, w = t >> 5;

    {
        int r = w;
        int ptr = g_head[r * NN + p];
        int c = 0;
        float4 acc = make_float4(0.f, 0.f, 0.f, 0.f);
        while (ptr) {
            int2 sn = g_en[ptr - 1];
            int ci = g_cid[sn.x];
            float4 hv = h4[ci * 32 + lane];
            acc.x += hv.x; acc.y += hv.y; acc.z += hv.z; acc.w += hv.w;
            c++;
            ptr = sn.y;
        }
        if (c > 1) {
            float s = 1.0f / (float)c;
            acc.x *= s; acc.y *= s; acc.z *= s; acc.w *= s;
        }
        *(float4*)&cs[r * 128 + lane * 4] = acc;
    }
    if (t < 128) {
        int cp = g_cid[p];
        cs[1024 + t] = g_h[(size_t)cp * 128 + t];
    }
    __syncthreads();

    int j = t & 63, q = t >> 6;
    float s = 0.f;
    int k0 = q * 288;
#pragma unroll 4
    for (int k = k0; k < k0 + 288; k++) {
        float wv = (k < 1024) ? W2[k * 64 + j] : root2[(k - 1024) * 64 + j];
        s += cs[k] * wv;
    }
    red[t] = s;
    __syncthreads();
    if (t < 64) {
        float o = red[t] + red[t + 64] + red[t + 128] + red[t + 192] + b2[j];
        float wp = 4.f * x[p * 128 + 0] + x[p * 128 + 1] + 2.f * x[p * 128 + 2];
        g_part[blockIdx.x * 64 + j] = o * wp;
        if (j == 0) g_wp[blockIdx.x] = wp;
    }

    // ---- last-block final reduction ----
    __threadfence();
    __syncthreads();
    if (t == 0) s_ticket = atomicAdd(&g_done, 1);
    __syncthreads();
    if (s_ticket == NP - 1) {
        __threadfence();
        if (t < 64) {
            float acc = 0.f;
            for (int i = 0; i < NP; i++) acc += g_part[i * 64 + t];
            float ws = 0.f;
            for (int i = 0; i < NP; i++) ws += g_wp[i];
            out[t] = acc / (ws + 1e-9f);
        }
        if (t == 0) g_done = 0;   // reset for next replay
    }
}

// ---------------------------------------------------------------- launch
extern "C" void kernel_launch(void* const* d_in, const int* in_sizes, int n_in,
                              void* d_out, int out_size) {
    const float* x     = (const float*)d_in[0];
    const int*   ei    = (const int*)  d_in[1];
    const int*   et    = (const int*)  d_in[2];
    const int*   pool  = (const int*)  d_in[3];
    const float* W1    = (const float*)d_in[4];
    const float* root1 = (const float*)d_in[5];
    const float* b1    = (const float*)d_in[6];
    const float* W2    = (const float*)d_in[7];
    const float* root2 = (const float*)d_in[8];
    const float* b2    = (const float*)d_in[9];
    float* out = (float*)d_out;
    (void)in_sizes; (void)n_in; (void)out_size;

    k_mark_pool<<<1, NP>>>(pool);
    k_mark_ws  <<<NB_MS + NB_WS + NB_HC, 256>>>(ei, W1, root1);
    k_cb       <<<NB_CP + NB_MS, 256>>>(ei, et);
    k_agg1     <<<2048, 256>>>(x);
    k_gemm1h   <<<CAP / 64, 256>>>(b1);
    k_pool     <<<NP, 256>>>(x, pool, W2, root2, b2, out);
}

// round 13
// speedup vs baseline: 1.1037x; 1.0593x over previous
#include <cuda_runtime.h>
#include <cuda_bf16.h>

#define NN   50000
#define NE   1600000
#define NR   8
#define KC   1152        // NR*128 + 128
#define CAP  16384
#define NP   256
#define DOUT 64

// ---- scratch (zero-initialized once by CUDA) ----
__device__ int   g_pmap[NN];          // 1 = pooled dst (idempotent across runs)
__device__ int   g_nf[NN];            // 1 = needed node (idempotent across runs)
__device__ int   g_cid[NN];
__device__ int   g_nodes[CAP];
__device__ int   g_counter;           // reset each run in k_mark_pool
__device__ unsigned g_done;           // pool-block ticket; last block resets to 0
__device__ int   g_head[NR * NN];     // head = edge+1, 0 = empty; CLEARED each run
__device__ int2  g_en[NE];            // {src, next(edge+1 or 0)}, rewritten each run
__device__ __align__(16) __nv_bfloat16 g_Ahi[(size_t)CAP * KC];
__device__ __align__(16) __nv_bfloat16 g_Alo[(size_t)CAP * KC];
__device__ __align__(16) __nv_bfloat16 g_Bhi[128 * KC];   // [outcol h][k]
__device__ __align__(16) __nv_bfloat16 g_Blo[128 * KC];
__device__ float g_h[(size_t)CAP * 128];
__device__ float g_part[NP * DOUT];
__device__ float g_wp[NP];

static __device__ __forceinline__ void split2(float v, __nv_bfloat16& hi, __nv_bfloat16& lo) {
    hi = __float2bfloat16_rn(v);
    lo = __float2bfloat16_rn(v - __bfloat162float(hi));
}

// warp mma m16n8k16 bf16 -> f32 accum (baseline PTX, HMMA on sm_103)
#define MMA16816(c, a, b) \
    asm volatile("mma.sync.aligned.m16n8k16.row.col.f32.bf16.bf16.f32 " \
                 "{%0,%1,%2,%3},{%4,%5,%6,%7},{%8,%9},{%0,%1,%2,%3};" \
                 : "+f"((c)[0]), "+f"((c)[1]), "+f"((c)[2]), "+f"((c)[3]) \
                 : "r"((a)[0]), "r"((a)[1]), "r"((a)[2]), "r"((a)[3]), \
                   "r"((b)[0]), "r"((b)[1]))

// ------------------------------------------- kernel 1: mark pool + resets
__global__ void k_mark_pool(const int* __restrict__ pool) {
    int p = pool[threadIdx.x];
    g_pmap[p] = 1;
    g_nf[p]   = 1;
    if (threadIdx.x == 0) { g_counter = 0; g_done = 0; }
}

// --------------------- kernel 2: mark_src || wsplit || head-clear
#define NB_MS ((NE + 255) / 256)
#define NB_WS ((128 * KC + 255) / 256)
#define NB_HC ((NR * NN / 4 + 255) / 256)    // clear as int4
__global__ void k_mark_ws(const int* __restrict__ ei,
                          const float* __restrict__ W1,
                          const float* __restrict__ root1) {
    int b = blockIdx.x;
    if (b < NB_MS) {
        int e = b * 256 + threadIdx.x;
        if (e < NE) {
            int dst = ei[NE + e];
            if (g_pmap[dst]) g_nf[ei[e]] = 1;
        }
    } else if (b < NB_MS + NB_WS) {
        int idx = (b - NB_MS) * 256 + threadIdx.x;   // 128*KC
        if (idx < 128 * KC) {
            int h = idx / KC, k = idx - h * KC;
            float w = (k < 1024) ? W1[k * 128 + h] : root1[(k - 1024) * 128 + h];
            __nv_bfloat16 hi, lo;
            split2(w, hi, lo);
            g_Bhi[idx] = hi;
            g_Blo[idx] = lo;
        }
    } else {
        int idx = (b - NB_MS - NB_WS) * 256 + threadIdx.x;   // int4 index
        if (idx < NR * NN / 4)
            ((int4*)g_head)[idx] = make_int4(0, 0, 0, 0);
    }
}

// ------------------------------------------- kernel 3: compact || build
#define NB_CP ((NN + 255) / 256)
__global__ void k_cb(const int* __restrict__ ei, const int* __restrict__ et) {
    int b = blockIdx.x;
    if (b < NB_CP) {
        int v = b * 256 + threadIdx.x;
        int lane = threadIdx.x & 31;
        int pred = (v < NN) && g_nf[v];
        unsigned mask = __ballot_sync(0xFFFFFFFF, pred);
        if (mask) {
            int leader = __ffs(mask) - 1;
            int base = 0;
            if (lane == leader) base = atomicAdd(&g_counter, __popc(mask));
            base = __shfl_sync(0xFFFFFFFF, base, leader);
            if (pred) {
                int c = base + __popc(mask & ((1u << lane) - 1));
                if (c < CAP) { g_cid[v] = c; g_nodes[c] = v; }
            }
        }
    } else {
        int e = (b - NB_CP) * 256 + threadIdx.x;
        if (e < NE) {
            int dst = ei[NE + e];
            if (g_nf[dst]) {
                int r = et[e];
                int prev = atomicExch(&g_head[r * NN + dst], e + 1);
                g_en[e] = make_int2(ei[e], prev);   // {src, next}
            }
        }
    }
}

// ------------------------------------------- kernel 4: layer-1 aggregation
// Task-per-warp, TWO tasks walked concurrently per warp;
// each chain hop is a single int2 load {src, next} (packed in k_cb).
__global__ void __launch_bounds__(256) k_agg1(const float* __restrict__ x) {
    const float4* x4 = (const float4*)x;
    int wid   = (blockIdx.x * blockDim.x + threadIdx.x) >> 5;
    int lane  = threadIdx.x & 31;
    int nwarp = (gridDim.x * blockDim.x) >> 5;
    int cnt   = min(g_counter, CAP);
    int ntask = cnt * 9;

    for (int base = wid * 2; base < ntask; base += nwarp * 2) {
        int    ptr_ [2];
        int    c_   [2];
        float4 acc_ [2];
        bool   chain[2];
#pragma unroll
        for (int s = 0; s < 2; s++) {
            int tt = base + s;
            ptr_[s] = 0;
            c_[s]   = 0;
            acc_[s] = make_float4(0.f, 0.f, 0.f, 0.f);
            chain[s] = false;
            if (tt < ntask) {
                int i = tt / 9;
                int r = tt - i * 9;
                int v = g_nodes[i];
                if (r == 8) {
                    acc_[s] = x4[v * 32 + lane];   // self row
                } else {
                    ptr_[s] = g_head[r * NN + v];
                    chain[s] = true;
                }
            }
        }

        while (ptr_[0] | ptr_[1]) {
            int2 sn[2];
#pragma unroll
            for (int s = 0; s < 2; s++)
                if (ptr_[s]) sn[s] = g_en[ptr_[s] - 1];
#pragma unroll
            for (int s = 0; s < 2; s++) {
                if (ptr_[s]) {
                    float4 xv = x4[sn[s].x * 32 + lane];
                    acc_[s].x += xv.x; acc_[s].y += xv.y;
                    acc_[s].z += xv.z; acc_[s].w += xv.w;
                    c_[s]++;
                    ptr_[s] = sn[s].y;
                }
            }
        }

#pragma unroll
        for (int s = 0; s < 2; s++) {
            int tt = base + s;
            if (tt >= ntask) continue;
            int i = tt / 9;
            int r = tt - i * 9;
            float4 a = acc_[s];
            if (chain[s] && c_[s] > 1) {
                float sc = 1.0f / (float)c_[s];
                a.x *= sc; a.y *= sc; a.z *= sc; a.w *= sc;
            }
            __nv_bfloat16 h[4], l[4];
            split2(a.x, h[0], l[0]);
            split2(a.y, h[1], l[1]);
            split2(a.z, h[2], l[2]);
            split2(a.w, h[3], l[3]);
            size_t off = (size_t)i * KC + r * 128 + lane * 4;
            *(uint2*)&g_Ahi[off] = *(uint2*)h;
            *(uint2*)&g_Alo[off] = *(uint2*)l;
        }
    }
}

// ------------------------------------------- kernel 5: layer-1 GEMM (HMMA)
// Register-prefetch pipeline: chunk c+1's global loads are issued during
// chunk c's MMA compute (one wave of ~132 blocks -> latency can't be hidden
// by occupancy, so hide it with ILP inside the block).
#define SA 40
#define NCH (KC / 32)
__global__ void __launch_bounds__(256) k_gemm1h(const float* __restrict__ b1) {
    __shared__ __align__(16) __nv_bfloat16 As[2][64 * SA];
    __shared__ __align__(16) __nv_bfloat16 Bs[2][128 * SA];
    int cnt  = min(g_counter, CAP);
    int row0 = blockIdx.x * 64;
    if (row0 >= cnt) return;
    int t = threadIdx.x;
    int lane = t & 31, wid = t >> 5;
    int wm = (wid & 1) * 32;
    int wn = (wid >> 1) * 32;
    int gr4 = lane >> 2;
    int kc  = (lane & 3) * 2;

    // per-thread staging coordinates
    int arow = t >> 2, aq = t & 3;           // A: row, 8-bf16 group
    int agr  = row0 + arow;
    int bh0  = t >> 2, bq0 = t & 3;          // B part 0
    int bh1  = (t + 256) >> 2, bq1 = t & 3;  // B part 1

    float acc[2][4][4];
#pragma unroll
    for (int mt = 0; mt < 2; mt++)
#pragma unroll
        for (int nt = 0; nt < 4; nt++)
#pragma unroll
            for (int j = 0; j < 4; j++) acc[mt][nt][j] = 0.f;

    uint4 pa_h, pa_l, pb_h0, pb_l0, pb_h1, pb_l1;

    // prefetch chunk 0
    {
        pa_h = make_uint4(0u, 0u, 0u, 0u); pa_l = pa_h;
        if (agr < cnt) {
            size_t s = (size_t)agr * KC + aq * 8;
            pa_h = *(const uint4*)&g_Ahi[s];
            pa_l = *(const uint4*)&g_Alo[s];
        }
        size_t s0 = (size_t)bh0 * KC + bq0 * 8;
        size_t s1 = (size_t)bh1 * KC + bq1 * 8;
        pb_h0 = *(const uint4*)&g_Bhi[s0];
        pb_l0 = *(const uint4*)&g_Blo[s0];
        pb_h1 = *(const uint4*)&g_Bhi[s1];
        pb_l1 = *(const uint4*)&g_Blo[s1];
    }

    for (int c = 0; c < NCH; c++) {
        // commit prefetched chunk c to smem
        *(uint4*)&As[0][arow * SA + aq * 8] = pa_h;
        *(uint4*)&As[1][arow * SA + aq * 8] = pa_l;
        *(uint4*)&Bs[0][bh0 * SA + bq0 * 8] = pb_h0;
        *(uint4*)&Bs[1][bh0 * SA + bq0 * 8] = pb_l0;
        *(uint4*)&Bs[0][bh1 * SA + bq1 * 8] = pb_h1;
        *(uint4*)&Bs[1][bh1 * SA + bq1 * 8] = pb_l1;
        __syncthreads();

        // issue chunk c+1 loads (overlap with compute below)
        if (c + 1 < NCH) {
            int k0 = (c + 1) * 32;
            pa_h = make_uint4(0u, 0u, 0u, 0u); pa_l = pa_h;
            if (agr < cnt) {
                size_t s = (size_t)agr * KC + k0 + aq * 8;
                pa_h = *(const uint4*)&g_Ahi[s];
                pa_l = *(const uint4*)&g_Alo[s];
            }
            size_t s0 = (size_t)bh0 * KC + k0 + bq0 * 8;
            size_t s1 = (size_t)bh1 * KC + k0 + bq1 * 8;
            pb_h0 = *(const uint4*)&g_Bhi[s0];
            pb_l0 = *(const uint4*)&g_Blo[s0];
            pb_h1 = *(const uint4*)&g_Bhi[s1];
            pb_l1 = *(const uint4*)&g_Blo[s1];
        }

#pragma unroll
        for (int ks = 0; ks < 32; ks += 16) {
            unsigned ah[2][4], al[2][4], bh[4][2], bl[4][2];
#pragma unroll
            for (int mt = 0; mt < 2; mt++) {
                int r0 = wm + mt * 16 + gr4;
                ah[mt][0] = *(const unsigned*)&As[0][(r0    ) * SA + ks + kc];
                ah[mt][1] = *(const unsigned*)&As[0][(r0 + 8) * SA + ks + kc];
                ah[mt][2] = *(const unsigned*)&As[0][(r0    ) * SA + ks + kc + 8];
                ah[mt][3] = *(const unsigned*)&As[0][(r0 + 8) * SA + ks + kc + 8];
                al[mt][0] = *(const unsigned*)&As[1][(r0    ) * SA + ks + kc];
                al[mt][1] = *(const unsigned*)&As[1][(r0 + 8) * SA + ks + kc];
                al[mt][2] = *(const unsigned*)&As[1][(r0    ) * SA + ks + kc + 8];
                al[mt][3] = *(const unsigned*)&As[1][(r0 + 8) * SA + ks + kc + 8];
            }
#pragma unroll
            for (int nt = 0; nt < 4; nt++) {
                int n0 = wn + nt * 8 + gr4;
                bh[nt][0] = *(const unsigned*)&Bs[0][n0 * SA + ks + kc];
                bh[nt][1] = *(const unsigned*)&Bs[0][n0 * SA + ks + kc + 8];
                bl[nt][0] = *(const unsigned*)&Bs[1][n0 * SA + ks + kc];
                bl[nt][1] = *(const unsigned*)&Bs[1][n0 * SA + ks + kc + 8];
            }
#pragma unroll
            for (int mt = 0; mt < 2; mt++)
#pragma unroll
                for (int nt = 0; nt < 4; nt++) {
                    MMA16816(acc[mt][nt], ah[mt], bh[nt]);
                    MMA16816(acc[mt][nt], al[mt], bh[nt]);
                    MMA16816(acc[mt][nt], ah[mt], bl[nt]);
                }
        }
        __syncthreads();
    }

#pragma unroll
    for (int mt = 0; mt < 2; mt++) {
#pragma unroll
        for (int nt = 0; nt < 4; nt++) {
            int col = wn + nt * 8 + kc;
            float b0 = b1[col], b1v = b1[col + 1];
            int r0 = row0 + wm + mt * 16 + gr4;
            int r1 = r0 + 8;
            if (r0 < cnt) {
                float2 o;
                o.x = fmaxf(acc[mt][nt][0] + b0, 0.f);
                o.y = fmaxf(acc[mt][nt][1] + b1v, 0.f);
                *(float2*)&g_h[(size_t)r0 * 128 + col] = o;
            }
            if (r1 < cnt) {
                float2 o;
                o.x = fmaxf(acc[mt][nt][2] + b0, 0.f);
                o.y = fmaxf(acc[mt][nt][3] + b1v, 0.f);
                *(float2*)&g_h[(size_t)r1 * 128 + col] = o;
            }
        }
    }
}

// ------------------------------------------- kernel 6: layer-2 + pool + final
__global__ void __launch_bounds__(256) k_pool(const float* __restrict__ x,
                                              const int* __restrict__ pool,
                                              const float* __restrict__ W2,
                                              const float* __restrict__ root2,
                                              const float* __restrict__ b2,
                                              float* __restrict__ out) {
    __shared__ float cs[KC];
    __shared__ float red[256];
    __shared__ unsigned s_ticket;
    const float4* h4 = (const float4*)g_h;
    int p = pool[blockIdx.x];
    int t = threadIdx.x;
    int lane = t & 31, w = t >> 5;

    {
        int r = w;
        int ptr = g_head[r * NN + p];
        int c = 0;
        float4 acc = make_float4(0.f, 0.f, 0.f, 0.f);
        while (ptr) {
            int2 sn = g_en[ptr - 1];
            int ci = g_cid[sn.x];
            float4 hv = h4[ci * 32 + lane];
            acc.x += hv.x; acc.y += hv.y; acc.z += hv.z; acc.w += hv.w;
            c++;
            ptr = sn.y;
        }
        if (c > 1) {
            float s = 1.0f / (float)c;
            acc.x *= s; acc.y *= s; acc.z *= s; acc.w *= s;
        }
        *(float4*)&cs[r * 128 + lane * 4] = acc;
    }
    if (t < 128) {
        int cp = g_cid[p];
        cs[1024 + t] = g_h[(size_t)cp * 128 + t];
    }
    __syncthreads();

    int j = t & 63, q = t >> 6;
    float s = 0.f;
    int k0 = q * 288;
#pragma unroll 4
    for (int k = k0; k < k0 + 288; k++) {
        float wv = (k < 1024) ? W2[k * 64 + j] : root2[(k - 1024) * 64 + j];
        s += cs[k] * wv;
    }
    red[t] = s;
    __syncthreads();
    if (t < 64) {
        float o = red[t] + red[t + 64] + red[t + 128] + red[t + 192] + b2[j];
        float wp = 4.f * x[p * 128 + 0] + x[p * 128 + 1] + 2.f * x[p * 128 + 2];
        g_part[blockIdx.x * 64 + j] = o * wp;
        if (j == 0) g_wp[blockIdx.x] = wp;
    }

    // ---- last-block final reduction ----
    __threadfence();
    __syncthreads();
    if (t == 0) s_ticket = atomicAdd(&g_done, 1);
    __syncthreads();
    if (s_ticket == NP - 1) {
        __threadfence();
        if (t < 64) {
            float acc = 0.f;
            for (int i = 0; i < NP; i++) acc += g_part[i * 64 + t];
            float ws = 0.f;
            for (int i = 0; i < NP; i++) ws += g_wp[i];
            out[t] = acc / (ws + 1e-9f);
        }
        if (t == 0) g_done = 0;   // reset for next replay
    }
}

// ---------------------------------------------------------------- launch
extern "C" void kernel_launch(void* const* d_in, const int* in_sizes, int n_in,
                              void* d_out, int out_size) {
    const float* x     = (const float*)d_in[0];
    const int*   ei    = (const int*)  d_in[1];
    const int*   et    = (const int*)  d_in[2];
    const int*   pool  = (const int*)  d_in[3];
    const float* W1    = (const float*)d_in[4];
    const float* root1 = (const float*)d_in[5];
    const float* b1    = (const float*)d_in[6];
    const float* W2    = (const float*)d_in[7];
    const float* root2 = (const float*)d_in[8];
    const float* b2    = (const float*)d_in[9];
    float* out = (float*)d_out;
    (void)in_sizes; (void)n_in; (void)out_size;

    k_mark_pool<<<1, NP>>>(pool);
    k_mark_ws  <<<NB_MS + NB_WS + NB_HC, 256>>>(ei, W1, root1);
    k_cb       <<<NB_CP + NB_MS, 256>>>(ei, et);
    k_agg1     <<<2048, 256>>>(x);
    k_gemm1h   <<<CAP / 64, 256>>>(b1);
    k_pool     <<<NP, 256>>>(x, pool, W2, root2, b2, out);
}

// round 14
// speedup vs baseline: 1.1433x; 1.0360x over previous
#include <cuda_runtime.h>
#include <cuda_bf16.h>

#define NN   50000
#define NE   1600000
#define NR   8
#define KC   1152        // NR*128 + 128
#define CAP  16384
#define NP   256
#define DOUT 64

// ---- scratch (zero-initialized once by CUDA) ----
__device__ int   g_pmap[NN];          // 1 = pooled dst (idempotent across runs)
__device__ int   g_nf[NN];            // 1 = needed node (idempotent across runs)
__device__ int   g_cid[NN];
__device__ int   g_nodes[CAP];
__device__ int   g_counter;           // reset each run in k_mark_pool
__device__ unsigned g_done;           // pool-block ticket; last block resets to 0
__device__ int   g_head[NR * NN];     // head = edge+1, 0 = empty; CLEARED each run
__device__ int2  g_en[NE];            // {src, next(edge+1 or 0)}, rewritten each run
__device__ __align__(16) __nv_bfloat16 g_Ahi[(size_t)CAP * KC];
__device__ __align__(16) __nv_bfloat16 g_Alo[(size_t)CAP * KC];
__device__ __align__(16) __nv_bfloat16 g_Bhi[128 * KC];   // [outcol h][k]
__device__ __align__(16) __nv_bfloat16 g_Blo[128 * KC];
__device__ float g_h[(size_t)CAP * 128];
__device__ float g_part[NP * DOUT];
__device__ float g_wp[NP];

static __device__ __forceinline__ void split2(float v, __nv_bfloat16& hi, __nv_bfloat16& lo) {
    hi = __float2bfloat16_rn(v);
    lo = __float2bfloat16_rn(v - __bfloat162float(hi));
}

__device__ __forceinline__ unsigned smem_u32(const void* p) {
    unsigned a;
    asm("{ .reg .u64 t; cvta.to.shared.u64 t, %1; cvt.u32.u64 %0, t; }" : "=r"(a) : "l"(p));
    return a;
}

// warp mma m16n8k16 bf16 -> f32 accum (baseline PTX, HMMA on sm_103)
#define MMA16816(c, a, b) \
    asm volatile("mma.sync.aligned.m16n8k16.row.col.f32.bf16.bf16.f32 " \
                 "{%0,%1,%2,%3},{%4,%5,%6,%7},{%8,%9},{%0,%1,%2,%3};" \
                 : "+f"((c)[0]), "+f"((c)[1]), "+f"((c)[2]), "+f"((c)[3]) \
                 : "r"((a)[0]), "r"((a)[1]), "r"((a)[2]), "r"((a)[3]), \
                   "r"((b)[0]), "r"((b)[1]))

// ldmatrix x4 (LDSM): 4 fragment regs in one shared-pipe op
#define LDSM4(r, addr) \
    asm volatile("ldmatrix.sync.aligned.m8n8.x4.shared.b16 {%0,%1,%2,%3}, [%4];" \
                 : "=r"((r)[0]), "=r"((r)[1]), "=r"((r)[2]), "=r"((r)[3]) \
                 : "r"(addr))

// ------------------------------------------- kernel 1: mark pool + resets
__global__ void k_mark_pool(const int* __restrict__ pool) {
    int p = pool[threadIdx.x];
    g_pmap[p] = 1;
    g_nf[p]   = 1;
    if (threadIdx.x == 0) { g_counter = 0; g_done = 0; }
}

// --------------------- kernel 2: mark_src || wsplit || head-clear
#define NB_MS ((NE + 255) / 256)
#define NB_WS ((128 * KC + 255) / 256)
#define NB_HC ((NR * NN / 4 + 255) / 256)    // clear as int4
__global__ void k_mark_ws(const int* __restrict__ ei,
                          const float* __restrict__ W1,
                          const float* __restrict__ root1) {
    int b = blockIdx.x;
    if (b < NB_MS) {
        int e = b * 256 + threadIdx.x;
        if (e < NE) {
            int dst = ei[NE + e];
            if (g_pmap[dst]) g_nf[ei[e]] = 1;
        }
    } else if (b < NB_MS + NB_WS) {
        int idx = (b - NB_MS) * 256 + threadIdx.x;   // 128*KC
        if (idx < 128 * KC) {
            int h = idx / KC, k = idx - h * KC;
            float w = (k < 1024) ? W1[k * 128 + h] : root1[(k - 1024) * 128 + h];
            __nv_bfloat16 hi, lo;
            split2(w, hi, lo);
            g_Bhi[idx] = hi;
            g_Blo[idx] = lo;
        }
    } else {
        int idx = (b - NB_MS - NB_WS) * 256 + threadIdx.x;   // int4 index
        if (idx < NR * NN / 4)
            ((int4*)g_head)[idx] = make_int4(0, 0, 0, 0);
    }
}

// ------------------------------------------- kernel 3: compact || build
#define NB_CP ((NN + 255) / 256)
__global__ void k_cb(const int* __restrict__ ei, const int* __restrict__ et) {
    int b = blockIdx.x;
    if (b < NB_CP) {
        int v = b * 256 + threadIdx.x;
        int lane = threadIdx.x & 31;
        int pred = (v < NN) && g_nf[v];
        unsigned mask = __ballot_sync(0xFFFFFFFF, pred);
        if (mask) {
            int leader = __ffs(mask) - 1;
            int base = 0;
            if (lane == leader) base = atomicAdd(&g_counter, __popc(mask));
            base = __shfl_sync(0xFFFFFFFF, base, leader);
            if (pred) {
                int c = base + __popc(mask & ((1u << lane) - 1));
                if (c < CAP) { g_cid[v] = c; g_nodes[c] = v; }
            }
        }
    } else {
        int e = (b - NB_CP) * 256 + threadIdx.x;
        if (e < NE) {
            int dst = ei[NE + e];
            if (g_nf[dst]) {
                int r = et[e];
                int prev = atomicExch(&g_head[r * NN + dst], e + 1);
                g_en[e] = make_int2(ei[e], prev);   // {src, next}
            }
        }
    }
}

// ------------------------------------------- kernel 4: layer-1 aggregation
// Task-per-warp, TWO tasks walked concurrently per warp;
// each chain hop is a single int2 load {src, next} (packed in k_cb).
__global__ void __launch_bounds__(256) k_agg1(const float* __restrict__ x) {
    const float4* x4 = (const float4*)x;
    int wid   = (blockIdx.x * blockDim.x + threadIdx.x) >> 5;
    int lane  = threadIdx.x & 31;
    int nwarp = (gridDim.x * blockDim.x) >> 5;
    int cnt   = min(g_counter, CAP);
    int ntask = cnt * 9;

    for (int base = wid * 2; base < ntask; base += nwarp * 2) {
        int    ptr_ [2];
        int    c_   [2];
        float4 acc_ [2];
        bool   chain[2];
#pragma unroll
        for (int s = 0; s < 2; s++) {
            int tt = base + s;
            ptr_[s] = 0;
            c_[s]   = 0;
            acc_[s] = make_float4(0.f, 0.f, 0.f, 0.f);
            chain[s] = false;
            if (tt < ntask) {
                int i = tt / 9;
                int r = tt - i * 9;
                int v = g_nodes[i];
                if (r == 8) {
                    acc_[s] = x4[v * 32 + lane];   // self row
                } else {
                    ptr_[s] = g_head[r * NN + v];
                    chain[s] = true;
                }
            }
        }

        while (ptr_[0] | ptr_[1]) {
            int2 sn[2];
#pragma unroll
            for (int s = 0; s < 2; s++)
                if (ptr_[s]) sn[s] = g_en[ptr_[s] - 1];
#pragma unroll
            for (int s = 0; s < 2; s++) {
                if (ptr_[s]) {
                    float4 xv = x4[sn[s].x * 32 + lane];
                    acc_[s].x += xv.x; acc_[s].y += xv.y;
                    acc_[s].z += xv.z; acc_[s].w += xv.w;
                    c_[s]++;
                    ptr_[s] = sn[s].y;
                }
            }
        }

#pragma unroll
        for (int s = 0; s < 2; s++) {
            int tt = base + s;
            if (tt >= ntask) continue;
            int i = tt / 9;
            int r = tt - i * 9;
            float4 a = acc_[s];
            if (chain[s] && c_[s] > 1) {
                float sc = 1.0f / (float)c_[s];
                a.x *= sc; a.y *= sc; a.z *= sc; a.w *= sc;
            }
            __nv_bfloat16 h[4], l[4];
            split2(a.x, h[0], l[0]);
            split2(a.y, h[1], l[1]);
            split2(a.z, h[2], l[2]);
            split2(a.w, h[3], l[3]);
            size_t off = (size_t)i * KC + r * 128 + lane * 4;
            *(uint2*)&g_Ahi[off] = *(uint2*)h;
            *(uint2*)&g_Alo[off] = *(uint2*)l;
        }
    }
}

// ------------------------------------------- kernel 5: layer-1 GEMM (HMMA)
// Register-prefetch pipeline + LDSM fragment loads (8 ldmatrix.x4 per warp
// per k16 instead of 32 scalar LDS).
#define SA 40
#define NCH (KC / 32)
__global__ void __launch_bounds__(256) k_gemm1h(const float* __restrict__ b1) {
    __shared__ __align__(16) __nv_bfloat16 As[2][64 * SA];
    __shared__ __align__(16) __nv_bfloat16 Bs[2][128 * SA];
    int cnt  = min(g_counter, CAP);
    int row0 = blockIdx.x * 64;
    if (row0 >= cnt) return;
    int t = threadIdx.x;
    int lane = t & 31, wid = t >> 5;
    int wm = (wid & 1) * 32;
    int wn = (wid >> 1) * 32;
    int gr4 = lane >> 2;
    int kc  = (lane & 3) * 2;

    // per-thread staging coordinates
    int arow = t >> 2, aq = t & 3;           // A: row, 8-bf16 group
    int agr  = row0 + arow;
    int bh0  = t >> 2, bq0 = t & 3;          // B part 0
    int bh1  = (t + 256) >> 2, bq1 = t & 3;  // B part 1

    // LDSM lane addressing:
    // A: mat0=rows0-7/k0-7, mat1=rows8-15/k0-7, mat2=rows0-7/k8-15, mat3=rows8-15/k8-15
    int arow_f = wm + (lane & 7) + ((lane >> 3) & 1) * 8;
    int akk    = (lane >> 4) * 8;
    // B: mat0=(n0-7,k0-7), mat1=(n0-7,k8-15), mat2=(n8-15,k0-7), mat3=(n8-15,k8-15)
    int bn_f   = wn + (lane & 7) + ((lane >> 4) & 1) * 8;
    int bkk    = ((lane >> 3) & 1) * 8;

    unsigned baseA0 = smem_u32(&As[0][0]);
    unsigned baseA1 = smem_u32(&As[1][0]);
    unsigned baseB0 = smem_u32(&Bs[0][0]);
    unsigned baseB1 = smem_u32(&Bs[1][0]);

    float acc[2][4][4];
#pragma unroll
    for (int mt = 0; mt < 2; mt++)
#pragma unroll
        for (int nt = 0; nt < 4; nt++)
#pragma unroll
            for (int j = 0; j < 4; j++) acc[mt][nt][j] = 0.f;

    uint4 pa_h, pa_l, pb_h0, pb_l0, pb_h1, pb_l1;

    // prefetch chunk 0
    {
        pa_h = make_uint4(0u, 0u, 0u, 0u); pa_l = pa_h;
        if (agr < cnt) {
            size_t s = (size_t)agr * KC + aq * 8;
            pa_h = *(const uint4*)&g_Ahi[s];
            pa_l = *(const uint4*)&g_Alo[s];
        }
        size_t s0 = (size_t)bh0 * KC + bq0 * 8;
        size_t s1 = (size_t)bh1 * KC + bq1 * 8;
        pb_h0 = *(const uint4*)&g_Bhi[s0];
        pb_l0 = *(const uint4*)&g_Blo[s0];
        pb_h1 = *(const uint4*)&g_Bhi[s1];
        pb_l1 = *(const uint4*)&g_Blo[s1];
    }

    for (int c = 0; c < NCH; c++) {
        // commit prefetched chunk c to smem
        *(uint4*)&As[0][arow * SA + aq * 8] = pa_h;
        *(uint4*)&As[1][arow * SA + aq * 8] = pa_l;
        *(uint4*)&Bs[0][bh0 * SA + bq0 * 8] = pb_h0;
        *(uint4*)&Bs[1][bh0 * SA + bq0 * 8] = pb_l0;
        *(uint4*)&Bs[0][bh1 * SA + bq1 * 8] = pb_h1;
        *(uint4*)&Bs[1][bh1 * SA + bq1 * 8] = pb_l1;
        __syncthreads();

        // issue chunk c+1 loads (overlap with compute below)
        if (c + 1 < NCH) {
            int k0 = (c + 1) * 32;
            pa_h = make_uint4(0u, 0u, 0u, 0u); pa_l = pa_h;
            if (agr < cnt) {
                size_t s = (size_t)agr * KC + k0 + aq * 8;
                pa_h = *(const uint4*)&g_Ahi[s];
                pa_l = *(const uint4*)&g_Alo[s];
            }
            size_t s0 = (size_t)bh0 * KC + k0 + bq0 * 8;
            size_t s1 = (size_t)bh1 * KC + k0 + bq1 * 8;
            pb_h0 = *(const uint4*)&g_Bhi[s0];
            pb_l0 = *(const uint4*)&g_Blo[s0];
            pb_h1 = *(const uint4*)&g_Bhi[s1];
            pb_l1 = *(const uint4*)&g_Blo[s1];
        }

#pragma unroll
        for (int ks = 0; ks < 32; ks += 16) {
            unsigned ah[2][4], al[2][4], bh[2][4], bl[2][4];
            unsigned ao = (unsigned)((arow_f * SA + ks + akk) * 2);
            unsigned bo = (unsigned)((bn_f * SA + ks + bkk) * 2);
            LDSM4(ah[0], baseA0 + ao);
            LDSM4(ah[1], baseA0 + ao + 16 * SA * 2);
            LDSM4(al[0], baseA1 + ao);
            LDSM4(al[1], baseA1 + ao + 16 * SA * 2);
            LDSM4(bh[0], baseB0 + bo);
            LDSM4(bh[1], baseB0 + bo + 16 * SA * 2);
            LDSM4(bl[0], baseB1 + bo);
            LDSM4(bl[1], baseB1 + bo + 16 * SA * 2);
#pragma unroll
            for (int mt = 0; mt < 2; mt++)
#pragma unroll
                for (int nt = 0; nt < 4; nt++) {
                    const unsigned* bhp = &bh[nt >> 1][(nt & 1) * 2];
                    const unsigned* blp = &bl[nt >> 1][(nt & 1) * 2];
                    MMA16816(acc[mt][nt], ah[mt], bhp);
                    MMA16816(acc[mt][nt], al[mt], bhp);
                    MMA16816(acc[mt][nt], ah[mt], blp);
                }
        }
        __syncthreads();
    }

#pragma unroll
    for (int mt = 0; mt < 2; mt++) {
#pragma unroll
        for (int nt = 0; nt < 4; nt++) {
            int col = wn + nt * 8 + kc;
            float b0 = b1[col], b1v = b1[col + 1];
            int r0 = row0 + wm + mt * 16 + gr4;
            int r1 = r0 + 8;
            if (r0 < cnt) {
                float2 o;
                o.x = fmaxf(acc[mt][nt][0] + b0, 0.f);
                o.y = fmaxf(acc[mt][nt][1] + b1v, 0.f);
                *(float2*)&g_h[(size_t)r0 * 128 + col] = o;
            }
            if (r1 < cnt) {
                float2 o;
                o.x = fmaxf(acc[mt][nt][2] + b0, 0.f);
                o.y = fmaxf(acc[mt][nt][3] + b1v, 0.f);
                *(float2*)&g_h[(size_t)r1 * 128 + col] = o;
            }
        }
    }
}

// ------------------------------------------- kernel 6: layer-2 + pool + final
__global__ void __launch_bounds__(256) k_pool(const float* __restrict__ x,
                                              const int* __restrict__ pool,
                                              const float* __restrict__ W2,
                                              const float* __restrict__ root2,
                                              const float* __restrict__ b2,
                                              float* __restrict__ out) {
    __shared__ float cs[KC];
    __shared__ float red[256];
    __shared__ unsigned s_ticket;
    const float4* h4 = (const float4*)g_h;
    int p = pool[blockIdx.x];
    int t = threadIdx.x;
    int lane = t & 31, w = t >> 5;

    {
        int r = w;
        int ptr = g_head[r * NN + p];
        int c = 0;
        float4 acc = make_float4(0.f, 0.f, 0.f, 0.f);
        while (ptr) {
            int2 sn = g_en[ptr - 1];
            int ci = g_cid[sn.x];
            float4 hv = h4[ci * 32 + lane];
            acc.x += hv.x; acc.y += hv.y; acc.z += hv.z; acc.w += hv.w;
            c++;
            ptr = sn.y;
        }
        if (c > 1) {
            float s = 1.0f / (float)c;
            acc.x *= s; acc.y *= s; acc.z *= s; acc.w *= s;
        }
        *(float4*)&cs[r * 128 + lane * 4] = acc;
    }
    if (t < 128) {
        int cp = g_cid[p];
        cs[1024 + t] = g_h[(size_t)cp * 128 + t];
    }
    __syncthreads();

    int j = t & 63, q = t >> 6;
    float s = 0.f;
    int k0 = q * 288;
#pragma unroll 4
    for (int k = k0; k < k0 + 288; k++) {
        float wv = (k < 1024) ? W2[k * 64 + j] : root2[(k - 1024) * 64 + j];
        s += cs[k] * wv;
    }
    red[t] = s;
    __syncthreads();
    if (t < 64) {
        float o = red[t] + red[t + 64] + red[t + 128] + red[t + 192] + b2[j];
        float wp = 4.f * x[p * 128 + 0] + x[p * 128 + 1] + 2.f * x[p * 128 + 2];
        g_part[blockIdx.x * 64 + j] = o * wp;
        if (j == 0) g_wp[blockIdx.x] = wp;
    }

    // ---- last-block final reduction ----
    __threadfence();
    __syncthreads();
    if (t == 0) s_ticket = atomicAdd(&g_done, 1);
    __syncthreads();
    if (s_ticket == NP - 1) {
        __threadfence();
        if (t < 64) {
            float acc = 0.f;
            for (int i = 0; i < NP; i++) acc += g_part[i * 64 + t];
            float ws = 0.f;
            for (int i = 0; i < NP; i++) ws += g_wp[i];
            out[t] = acc / (ws + 1e-9f);
        }
        if (t == 0) g_done = 0;   // reset for next replay
    }
}

// ---------------------------------------------------------------- launch
extern "C" void kernel_launch(void* const* d_in, const int* in_sizes, int n_in,
                              void* d_out, int out_size) {
    const float* x     = (const float*)d_in[0];
    const int*   ei    = (const int*)  d_in[1];
    const int*   et    = (const int*)  d_in[2];
    const int*   pool  = (const int*)  d_in[3];
    const float* W1    = (const float*)d_in[4];
    const float* root1 = (const float*)d_in[5];
    const float* b1    = (const float*)d_in[6];
    const float* W2    = (const float*)d_in[7];
    const float* root2 = (const float*)d_in[8];
    const float* b2    = (const float*)d_in[9];
    float* out = (float*)d_out;
    (void)in_sizes; (void)n_in; (void)out_size;

    k_mark_pool<<<1, NP>>>(pool);
    k_mark_ws  <<<NB_MS + NB_WS + NB_HC, 256>>>(ei, W1, root1);
    k_cb       <<<NB_CP + NB_MS, 256>>>(ei, et);
    k_agg1     <<<2048, 256>>>(x);
    k_gemm1h   <<<CAP / 64, 256>>>(b1);
    k_pool     <<<NP, 256>>>(x, pool, W2, root2, b2, out);
}

// round 15
// speedup vs baseline: 1.1732x; 1.0261x over previous
#include <cuda_runtime.h>
#include <cuda_bf16.h>

#define NN   50000
#define NE   1600000
#define NR   8
#define KC   1152        // NR*128 + 128
#define CAP  16384
#define NP   256
#define DOUT 64

#define GRID_WAIT() asm volatile("griddepcontrol.wait;" ::: "memory")

// ---- scratch (zero-initialized once by CUDA) ----
__device__ int   g_pmap[NN];          // 1 = pooled dst (idempotent across runs)
__device__ int   g_nf[NN];            // 1 = needed node (idempotent across runs)
__device__ int   g_cid[NN];
__device__ int   g_nodes[CAP];
__device__ int   g_counter;           // reset each run in k_mark_pool
__device__ unsigned g_done;           // pool-block ticket; last block resets to 0
__device__ int   g_head[NR * NN];     // head = edge+1, 0 = empty; CLEARED each run
__device__ int2  g_en[NE];            // {src, next(edge+1 or 0)}, rewritten each run
__device__ __align__(16) __nv_bfloat16 g_Ahi[(size_t)CAP * KC];
__device__ __align__(16) __nv_bfloat16 g_Alo[(size_t)CAP * KC];
__device__ __align__(16) __nv_bfloat16 g_Bhi[128 * KC];   // [outcol h][k]
__device__ __align__(16) __nv_bfloat16 g_Blo[128 * KC];
__device__ float g_h[(size_t)CAP * 128];
__device__ float g_part[NP * DOUT];
__device__ float g_wp[NP];

static __device__ __forceinline__ void split2(float v, __nv_bfloat16& hi, __nv_bfloat16& lo) {
    hi = __float2bfloat16_rn(v);
    lo = __float2bfloat16_rn(v - __bfloat162float(hi));
}

__device__ __forceinline__ unsigned smem_u32(const void* p) {
    unsigned a;
    asm("{ .reg .u64 t; cvta.to.shared.u64 t, %1; cvt.u32.u64 %0, t; }" : "=r"(a) : "l"(p));
    return a;
}

// warp mma m16n8k16 bf16 -> f32 accum (baseline PTX, HMMA on sm_103)
#define MMA16816(c, a, b) \
    asm volatile("mma.sync.aligned.m16n8k16.row.col.f32.bf16.bf16.f32 " \
                 "{%0,%1,%2,%3},{%4,%5,%6,%7},{%8,%9},{%0,%1,%2,%3};" \
                 : "+f"((c)[0]), "+f"((c)[1]), "+f"((c)[2]), "+f"((c)[3]) \
                 : "r"((a)[0]), "r"((a)[1]), "r"((a)[2]), "r"((a)[3]), \
                   "r"((b)[0]), "r"((b)[1]))

// ldmatrix x4 (LDSM): 4 fragment regs in one shared-pipe op
#define LDSM4(r, addr) \
    asm volatile("ldmatrix.sync.aligned.m8n8.x4.shared.b16 {%0,%1,%2,%3}, [%4];" \
                 : "=r"((r)[0]), "=r"((r)[1]), "=r"((r)[2]), "=r"((r)[3]) \
                 : "r"(addr))

// ------------------------------------------- kernel 1: mark pool + resets
__global__ void k_mark_pool(const int* __restrict__ pool) {
    int p = pool[threadIdx.x];
    g_pmap[p] = 1;
    g_nf[p]   = 1;
    if (threadIdx.x == 0) { g_counter = 0; g_done = 0; }
}

// --------------------- kernel 2: mark_src || wsplit || head-clear
#define NB_MS ((NE + 255) / 256)
#define NB_WS ((128 * KC + 255) / 256)
#define NB_HC ((NR * NN / 4 + 255) / 256)    // clear as int4
__global__ void k_mark_ws(const int* __restrict__ ei,
                          const float* __restrict__ W1,
                          const float* __restrict__ root1) {
    int b = blockIdx.x;
    if (b < NB_MS) {
        GRID_WAIT();                        // needs g_pmap from k_mark_pool
        int e = b * 256 + threadIdx.x;
        if (e < NE) {
            int dst = ei[NE + e];
            if (g_pmap[dst]) g_nf[ei[e]] = 1;
        }
    } else if (b < NB_MS + NB_WS) {
        // weight split: independent of predecessor
        int idx = (b - NB_MS) * 256 + threadIdx.x;   // 128*KC
        if (idx < 128 * KC) {
            int h = idx / KC, k = idx - h * KC;
            float w = (k < 1024) ? W1[k * 128 + h] : root1[(k - 1024) * 128 + h];
            __nv_bfloat16 hi, lo;
            split2(w, hi, lo);
            g_Bhi[idx] = hi;
            g_Blo[idx] = lo;
        }
    } else {
        // head clear: independent of predecessor
        int idx = (b - NB_MS - NB_WS) * 256 + threadIdx.x;   // int4 index
        if (idx < NR * NN / 4)
            ((int4*)g_head)[idx] = make_int4(0, 0, 0, 0);
    }
}

// ------------------------------------------- kernel 3: compact || build
#define NB_CP ((NN + 255) / 256)
__global__ void k_cb(const int* __restrict__ ei, const int* __restrict__ et) {
    GRID_WAIT();                            // needs g_nf + cleared heads
    int b = blockIdx.x;
    if (b < NB_CP) {
        int v = b * 256 + threadIdx.x;
        int lane = threadIdx.x & 31;
        int pred = (v < NN) && g_nf[v];
        unsigned mask = __ballot_sync(0xFFFFFFFF, pred);
        if (mask) {
            int leader = __ffs(mask) - 1;
            int base = 0;
            if (lane == leader) base = atomicAdd(&g_counter, __popc(mask));
            base = __shfl_sync(0xFFFFFFFF, base, leader);
            if (pred) {
                int c = base + __popc(mask & ((1u << lane) - 1));
                if (c < CAP) { g_cid[v] = c; g_nodes[c] = v; }
            }
        }
    } else {
        int e = (b - NB_CP) * 256 + threadIdx.x;
        if (e < NE) {
            int dst = ei[NE + e];
            if (g_nf[dst]) {
                int r = et[e];
                int prev = atomicExch(&g_head[r * NN + dst], e + 1);
                g_en[e] = make_int2(ei[e], prev);   // {src, next}
            }
        }
    }
}

// ------------------------------------------- kernel 4: layer-1 aggregation
// Task-per-warp, TWO tasks walked concurrently per warp;
// each chain hop is a single int2 load {src, next} (packed in k_cb).
__global__ void __launch_bounds__(256) k_agg1(const float* __restrict__ x) {
    GRID_WAIT();                            // needs g_nodes/g_counter/heads/g_en
    const float4* x4 = (const float4*)x;
    int wid   = (blockIdx.x * blockDim.x + threadIdx.x) >> 5;
    int lane  = threadIdx.x & 31;
    int nwarp = (gridDim.x * blockDim.x) >> 5;
    int cnt   = min(g_counter, CAP);
    int ntask = cnt * 9;

    for (int base = wid * 2; base < ntask; base += nwarp * 2) {
        int    ptr_ [2];
        int    c_   [2];
        float4 acc_ [2];
        bool   chain[2];
#pragma unroll
        for (int s = 0; s < 2; s++) {
            int tt = base + s;
            ptr_[s] = 0;
            c_[s]   = 0;
            acc_[s] = make_float4(0.f, 0.f, 0.f, 0.f);
            chain[s] = false;
            if (tt < ntask) {
                int i = tt / 9;
                int r = tt - i * 9;
                int v = g_nodes[i];
                if (r == 8) {
                    acc_[s] = x4[v * 32 + lane];   // self row
                } else {
                    ptr_[s] = g_head[r * NN + v];
                    chain[s] = true;
                }
            }
        }

        while (ptr_[0] | ptr_[1]) {
            int2 sn[2];
#pragma unroll
            for (int s = 0; s < 2; s++)
                if (ptr_[s]) sn[s] = g_en[ptr_[s] - 1];
#pragma unroll
            for (int s = 0; s < 2; s++) {
                if (ptr_[s]) {
                    float4 xv = x4[sn[s].x * 32 + lane];
                    acc_[s].x += xv.x; acc_[s].y += xv.y;
                    acc_[s].z += xv.z; acc_[s].w += xv.w;
                    c_[s]++;
                    ptr_[s] = sn[s].y;
                }
            }
        }

#pragma unroll
        for (int s = 0; s < 2; s++) {
            int tt = base + s;
            if (tt >= ntask) continue;
            int i = tt / 9;
            int r = tt - i * 9;
            float4 a = acc_[s];
            if (chain[s] && c_[s] > 1) {
                float sc = 1.0f / (float)c_[s];
                a.x *= sc; a.y *= sc; a.z *= sc; a.w *= sc;
            }
            __nv_bfloat16 h[4], l[4];
            split2(a.x, h[0], l[0]);
            split2(a.y, h[1], l[1]);
            split2(a.z, h[2], l[2]);
            split2(a.w, h[3], l[3]);
            size_t off = (size_t)i * KC + r * 128 + lane * 4;
            *(uint2*)&g_Ahi[off] = *(uint2*)h;
            *(uint2*)&g_Alo[off] = *(uint2*)l;
        }
    }
}

// ------------------------------------------- kernel 5: layer-1 GEMM (HMMA)
// Register-prefetch pipeline + LDSM fragment loads.
#define SA 40
#define NCH (KC / 32)
__global__ void __launch_bounds__(256) k_gemm1h(const float* __restrict__ b1) {
    GRID_WAIT();                            // needs g_Ahi/g_Alo from k_agg1
    __shared__ __align__(16) __nv_bfloat16 As[2][64 * SA];
    __shared__ __align__(16) __nv_bfloat16 Bs[2][128 * SA];
    int cnt  = min(g_counter, CAP);
    int row0 = blockIdx.x * 64;
    if (row0 >= cnt) return;
    int t = threadIdx.x;
    int lane = t & 31, wid = t >> 5;
    int wm = (wid & 1) * 32;
    int wn = (wid >> 1) * 32;
    int gr4 = lane >> 2;
    int kc  = (lane & 3) * 2;

    // per-thread staging coordinates
    int arow = t >> 2, aq = t & 3;           // A: row, 8-bf16 group
    int agr  = row0 + arow;
    int bh0  = t >> 2, bq0 = t & 3;          // B part 0
    int bh1  = (t + 256) >> 2, bq1 = t & 3;  // B part 1

    // LDSM lane addressing
    int arow_f = wm + (lane & 7) + ((lane >> 3) & 1) * 8;
    int akk    = (lane >> 4) * 8;
    int bn_f   = wn + (lane & 7) + ((lane >> 4) & 1) * 8;
    int bkk    = ((lane >> 3) & 1) * 8;

    unsigned baseA0 = smem_u32(&As[0][0]);
    unsigned baseA1 = smem_u32(&As[1][0]);
    unsigned baseB0 = smem_u32(&Bs[0][0]);
    unsigned baseB1 = smem_u32(&Bs[1][0]);

    float acc[2][4][4];
#pragma unroll
    for (int mt = 0; mt < 2; mt++)
#pragma unroll
        for (int nt = 0; nt < 4; nt++)
#pragma unroll
            for (int j = 0; j < 4; j++) acc[mt][nt][j] = 0.f;

    uint4 pa_h, pa_l, pb_h0, pb_l0, pb_h1, pb_l1;

    // prefetch chunk 0
    {
        pa_h = make_uint4(0u, 0u, 0u, 0u); pa_l = pa_h;
        if (agr < cnt) {
            size_t s = (size_t)agr * KC + aq * 8;
            pa_h = *(const uint4*)&g_Ahi[s];
            pa_l = *(const uint4*)&g_Alo[s];
        }
        size_t s0 = (size_t)bh0 * KC + bq0 * 8;
        size_t s1 = (size_t)bh1 * KC + bq1 * 8;
        pb_h0 = *(const uint4*)&g_Bhi[s0];
        pb_l0 = *(const uint4*)&g_Blo[s0];
        pb_h1 = *(const uint4*)&g_Bhi[s1];
        pb_l1 = *(const uint4*)&g_Blo[s1];
    }

    for (int c = 0; c < NCH; c++) {
        *(uint4*)&As[0][arow * SA + aq * 8] = pa_h;
        *(uint4*)&As[1][arow * SA + aq * 8] = pa_l;
        *(uint4*)&Bs[0][bh0 * SA + bq0 * 8] = pb_h0;
        *(uint4*)&Bs[1][bh0 * SA + bq0 * 8] = pb_l0;
        *(uint4*)&Bs[0][bh1 * SA + bq1 * 8] = pb_h1;
        *(uint4*)&Bs[1][bh1 * SA + bq1 * 8] = pb_l1;
        __syncthreads();

        if (c + 1 < NCH) {
            int k0 = (c + 1) * 32;
            pa_h = make_uint4(0u, 0u, 0u, 0u); pa_l = pa_h;
            if (agr < cnt) {
                size_t s = (size_t)agr * KC + k0 + aq * 8;
                pa_h = *(const uint4*)&g_Ahi[s];
                pa_l = *(const uint4*)&g_Alo[s];
            }
            size_t s0 = (size_t)bh0 * KC + k0 + bq0 * 8;
            size_t s1 = (size_t)bh1 * KC + k0 + bq1 * 8;
            pb_h0 = *(const uint4*)&g_Bhi[s0];
            pb_l0 = *(const uint4*)&g_Blo[s0];
            pb_h1 = *(const uint4*)&g_Bhi[s1];
            pb_l1 = *(const uint4*)&g_Blo[s1];
        }

#pragma unroll
        for (int ks = 0; ks < 32; ks += 16) {
            unsigned ah[2][4], al[2][4], bh[2][4], bl[2][4];
            unsigned ao = (unsigned)((arow_f * SA + ks + akk) * 2);
            unsigned bo = (unsigned)((bn_f * SA + ks + bkk) * 2);
            LDSM4(ah[0], baseA0 + ao);
            LDSM4(ah[1], baseA0 + ao + 16 * SA * 2);
            LDSM4(al[0], baseA1 + ao);
            LDSM4(al[1], baseA1 + ao + 16 * SA * 2);
            LDSM4(bh[0], baseB0 + bo);
            LDSM4(bh[1], baseB0 + bo + 16 * SA * 2);
            LDSM4(bl[0], baseB1 + bo);
            LDSM4(bl[1], baseB1 + bo + 16 * SA * 2);
#pragma unroll
            for (int mt = 0; mt < 2; mt++)
#pragma unroll
                for (int nt = 0; nt < 4; nt++) {
                    const unsigned* bhp = &bh[nt >> 1][(nt & 1) * 2];
                    const unsigned* blp = &bl[nt >> 1][(nt & 1) * 2];
                    MMA16816(acc[mt][nt], ah[mt], bhp);
                    MMA16816(acc[mt][nt], al[mt], bhp);
                    MMA16816(acc[mt][nt], ah[mt], blp);
                }
        }
        __syncthreads();
    }

#pragma unroll
    for (int mt = 0; mt < 2; mt++) {
#pragma unroll
        for (int nt = 0; nt < 4; nt++) {
            int col = wn + nt * 8 + kc;
            float b0 = b1[col], b1v = b1[col + 1];
            int r0 = row0 + wm + mt * 16 + gr4;
            int r1 = r0 + 8;
            if (r0 < cnt) {
                float2 o;
                o.x = fmaxf(acc[mt][nt][0] + b0, 0.f);
                o.y = fmaxf(acc[mt][nt][1] + b1v, 0.f);
                *(float2*)&g_h[(size_t)r0 * 128 + col] = o;
            }
            if (r1 < cnt) {
                float2 o;
                o.x = fmaxf(acc[mt][nt][2] + b0, 0.f);
                o.y = fmaxf(acc[mt][nt][3] + b1v, 0.f);
                *(float2*)&g_h[(size_t)r1 * 128 + col] = o;
            }
        }
    }
}

// ------------------------------------------- kernel 6: layer-2 + pool + final
// Phase 0 (pre-wait): collect chain compact-ids (k_cb products — complete long
// before this kernel can run). Post-wait: indexed h gathers with 4-way MLP.
#define ECAP 192
__global__ void __launch_bounds__(256) k_pool(const float* __restrict__ x,
                                              const int* __restrict__ pool,
                                              const float* __restrict__ W2,
                                              const float* __restrict__ root2,
                                              const float* __restrict__ b2,
                                              float* __restrict__ out) {
    __shared__ float cs[KC];
    __shared__ float red[256];
    __shared__ int   s_ci[NR * ECAP];
    __shared__ int   s_cnt[NR];
    __shared__ unsigned s_ticket;
    int p = pool[blockIdx.x];
    int t = threadIdx.x;
    int lane = t & 31, w = t >> 5;

    // phase 0: warp-uniform chain walk, record cids (no g_h reads)
    {
        int ptr = g_head[w * NN + p];
        int c = 0;
        while (ptr && c < ECAP) {
            int2 sn = g_en[ptr - 1];
            int ci = g_cid[sn.x];
            if (lane == 0) s_ci[w * ECAP + c] = ci;
            c++;
            ptr = sn.y;
        }
        if (lane == 0) s_cnt[w] = c;
    }
    __syncthreads();
    GRID_WAIT();                            // g_h must be ready from here on

    {
        const float4* h4 = (const float4*)g_h;
        int c = s_cnt[w];
        float4 acc = make_float4(0.f, 0.f, 0.f, 0.f);
        int j = 0;
        for (; j + 4 <= c; j += 4) {
            float4 a0 = h4[s_ci[w * ECAP + j    ] * 32 + lane];
            float4 a1 = h4[s_ci[w * ECAP + j + 1] * 32 + lane];
            float4 a2 = h4[s_ci[w * ECAP + j + 2] * 32 + lane];
            float4 a3 = h4[s_ci[w * ECAP + j + 3] * 32 + lane];
            acc.x += (a0.x + a1.x) + (a2.x + a3.x);
            acc.y += (a0.y + a1.y) + (a2.y + a3.y);
            acc.z += (a0.z + a1.z) + (a2.z + a3.z);
            acc.w += (a0.w + a1.w) + (a2.w + a3.w);
        }
        for (; j < c; j++) {
            float4 a0 = h4[s_ci[w * ECAP + j] * 32 + lane];
            acc.x += a0.x; acc.y += a0.y; acc.z += a0.z; acc.w += a0.w;
        }
        if (c > 1) {
            float s = 1.0f / (float)c;
            acc.x *= s; acc.y *= s; acc.z *= s; acc.w *= s;
        }
        *(float4*)&cs[w * 128 + lane * 4] = acc;
    }
    if (t < 128) {
        int cp = g_cid[p];
        cs[1024 + t] = g_h[(size_t)cp * 128 + t];
    }
    __syncthreads();

    int j = t & 63, q = t >> 6;
    float s = 0.f;
    int k0 = q * 288;
#pragma unroll 4
    for (int k = k0; k < k0 + 288; k++) {
        float wv = (k < 1024) ? W2[k * 64 + j] : root2[(k - 1024) * 64 + j];
        s += cs[k] * wv;
    }
    red[t] = s;
    __syncthreads();
    if (t < 64) {
        float o = red[t] + red[t + 64] + red[t + 128] + red[t + 192] + b2[j];
        float wp = 4.f * x[p * 128 + 0] + x[p * 128 + 1] + 2.f * x[p * 128 + 2];
        g_part[blockIdx.x * 64 + j] = o * wp;
        if (j == 0) g_wp[blockIdx.x] = wp;
    }

    // ---- last-block final reduction ----
    __threadfence();
    __syncthreads();
    if (t == 0) s_ticket = atomicAdd(&g_done, 1);
    __syncthreads();
    if (s_ticket == NP - 1) {
        __threadfence();
        if (t < 64) {
            float acc = 0.f;
            for (int i = 0; i < NP; i++) acc += g_part[i * 64 + t];
            float ws = 0.f;
            for (int i = 0; i < NP; i++) ws += g_wp[i];
            out[t] = acc / (ws + 1e-9f);
        }
        if (t == 0) g_done = 0;   // reset for next replay
    }
}

// ---------------------------------------------------------------- launch
template <typename... Args>
static void launch_pdl(void (*kern)(Args...), dim3 grid, dim3 block, bool pdl,
                       Args... args) {
    cudaLaunchConfig_t cfg = {};
    cfg.gridDim = grid;
    cfg.blockDim = block;
    cudaLaunchAttribute at[1];
    if (pdl) {
        at[0].id = cudaLaunchAttributeProgrammaticStreamSerialization;
        at[0].val.programmaticStreamSerializationAllowed = 1;
        cfg.attrs = at;
        cfg.numAttrs = 1;
    }
    cudaLaunchKernelEx(&cfg, kern, args...);
}

extern "C" void kernel_launch(void* const* d_in, const int* in_sizes, int n_in,
                              void* d_out, int out_size) {
    const float* x     = (const float*)d_in[0];
    const int*   ei    = (const int*)  d_in[1];
    const int*   et    = (const int*)  d_in[2];
    const int*   pool  = (const int*)  d_in[3];
    const float* W1    = (const float*)d_in[4];
    const float* root1 = (const float*)d_in[5];
    const float* b1    = (const float*)d_in[6];
    const float* W2    = (const float*)d_in[7];
    const float* root2 = (const float*)d_in[8];
    const float* b2    = (const float*)d_in[9];
    float* out = (float*)d_out;
    (void)in_sizes; (void)n_in; (void)out_size;

    launch_pdl(k_mark_pool, dim3(1), dim3(NP), false, pool);
    launch_pdl(k_mark_ws, dim3(NB_MS + NB_WS + NB_HC), dim3(256), true, ei, W1, root1);
    launch_pdl(k_cb, dim3(NB_CP + NB_MS), dim3(256), true, ei, et);
    launch_pdl(k_agg1, dim3(2048), dim3(256), true, x);
    launch_pdl(k_gemm1h, dim3(CAP / 64), dim3(256), true, b1);
    launch_pdl(k_pool, dim3(NP), dim3(256), true, x, pool, W2, root2, b2, out);
}